// round 7
// baseline (speedup 1.0000x reference)
#include <cuda_runtime.h>
#include <cuda_bf16.h>

#define BINS 10
#define TPB  256
#define CTAS_PER_SM 5
#define GRID (148 * CTAS_PER_SM)

// __device__ globals zero-initialized at load; last block resets them after
// finalizing -> every launch / graph replay starts clean. Single launch node.
__device__ double             g_loss_sum[BINS];
__device__ unsigned long long g_count[BINS];
__device__ unsigned int       g_ticket;

// One element's accumulate into a given replica array.
__device__ __forceinline__ void ghm_elem(float2* __restrict__ acc, int tid,
                                         float xx, float tt)
{
    float g  = fabsf(xx - tt);
    int   b  = (int)(g * 9.9999f);          // g < 1 strictly -> b in [0,9]
    float l1 = __log2f(xx);
    float l2 = __log2f(1.0f - xx);
    float loss2 = fmaf(tt, l1 - l2, l2);    // scaled by -ln2 at finalize
    int addr = b * TPB + tid;
    float2 a = acc[addr];
    a.x += loss2;
    a.y += 1.0f;
    acc[addr] = a;
}

__global__ __launch_bounds__(TPB, CTAS_PER_SM)
void ghm_fused_kernel(const float4* __restrict__ x4,
                      const float4* __restrict__ t4,
                      const float*  __restrict__ x1,
                      const float*  __restrict__ t1,
                      int n4, int n, long long N,
                      float* __restrict__ out)
{
    // TWO DISTINCT shared arrays -> compiler-provable non-aliasing between the
    // even-element and odd-element RMW chains; they interleave instead of
    // serializing. Bank index is tid-determined regardless of bin: conflict-free.
    __shared__ float2 accA[BINS * TPB];
    __shared__ float2 accB[BINS * TPB];

    const int tid = threadIdx.x;
#pragma unroll
    for (int k = 0; k < BINS; k++) {
        accA[k * TPB + tid] = make_float2(0.0f, 0.0f);
        accB[k * TPB + tid] = make_float2(0.0f, 0.0f);
    }
    __syncthreads();

    const int stride = gridDim.x * blockDim.x;
    int i = blockIdx.x * blockDim.x + tid;

    // 3-stage software pipeline: keep 2 iterations of loads (4x LDG.128) in flight.
    if (i < n4) {
        float4 xv0 = x4[i];
        float4 tv0 = t4[i];
        float4 xv1, tv1;
        bool have1 = (i + stride < n4);
        if (have1) { xv1 = x4[i + stride]; tv1 = t4[i + stride]; }

        for (; i + 2 * stride < n4; i += stride) {
            float4 xn = x4[i + 2 * stride];
            float4 tn = t4[i + 2 * stride];
            ghm_elem(accA, tid, xv0.x, tv0.x);
            ghm_elem(accB, tid, xv0.y, tv0.y);
            ghm_elem(accA, tid, xv0.z, tv0.z);
            ghm_elem(accB, tid, xv0.w, tv0.w);
            xv0 = xv1; tv0 = tv1;
            xv1 = xn;  tv1 = tn;
        }
        // drain
        ghm_elem(accA, tid, xv0.x, tv0.x);
        ghm_elem(accB, tid, xv0.y, tv0.y);
        ghm_elem(accA, tid, xv0.z, tv0.z);
        ghm_elem(accB, tid, xv0.w, tv0.w);
        if (have1) {
            ghm_elem(accA, tid, xv1.x, tv1.x);
            ghm_elem(accB, tid, xv1.y, tv1.y);
            ghm_elem(accA, tid, xv1.z, tv1.z);
            ghm_elem(accB, tid, xv1.w, tv1.w);
        }
    }

    // scalar tail (n % 4): block 0 only
    if (blockIdx.x == 0) {
        for (int k = n4 * 4 + tid; k < n; k += blockDim.x)
            ghm_elem(accA, tid, x1[k], t1[k]);
    }
    __syncthreads();

    // merge replicas, then block tree reduction over tid for all bins
#pragma unroll
    for (int k = 0; k < BINS; k++) {
        float2 a = accA[k * TPB + tid];
        float2 b = accB[k * TPB + tid];
        a.x += b.x; a.y += b.y;
        accA[k * TPB + tid] = a;
    }
    __syncthreads();

    for (int s = TPB / 2; s > 0; s >>= 1) {
        if (tid < s) {
#pragma unroll
            for (int k = 0; k < BINS; k++) {
                float2 a = accA[k * TPB + tid];
                float2 b = accA[k * TPB + tid + s];
                a.x += b.x; a.y += b.y;
                accA[k * TPB + tid] = a;
            }
        }
        __syncthreads();
    }

    if (tid < BINS) {
        float2 a = accA[tid * TPB];
        atomicAdd(&g_loss_sum[tid], (double)a.x);
        atomicAdd(&g_count[tid], (unsigned long long)(a.y + 0.5f));
    }

    // last-block finalize + reset (fused epilogue)
    __shared__ unsigned int s_is_last;
    if (tid == 0) {
        __threadfence();
        unsigned int prev = atomicAdd(&g_ticket, 1u);
        s_is_last = (prev == (unsigned int)gridDim.x - 1u) ? 1u : 0u;
    }
    __syncthreads();

    if (s_is_last && tid == 0) {
        __threadfence();                     // all blocks' atomics visible
        const double NEG_LN2 = -0.6931471805599453;
        float nonempty = 0.0f;
#pragma unroll
        for (int k = 0; k < BINS; k++)
            nonempty += (g_count[k] > 0ull) ? 1.0f : 0.0f;

        const float Nf = (float)N;
        double total = 0.0;
#pragma unroll
        for (int k = 0; k < BINS; k++) {
            float cntf = (float)g_count[k];              // match jnp f32 cast
            float gd   = fmaxf(cntf * nonempty, 1.0f);
            float beta = Nf / gd;
            total += (double)beta * (NEG_LN2 * g_loss_sum[k]);
        }
        out[0] = (float)(total / (double)N);

        // reset for next launch / graph replay
#pragma unroll
        for (int k = 0; k < BINS; k++) {
            g_loss_sum[k] = 0.0;
            g_count[k]    = 0ull;
        }
        __threadfence();
        g_ticket = 0u;
    }
}

extern "C" void kernel_launch(void* const* d_in, const int* in_sizes, int n_in,
                              void* d_out, int out_size)
{
    const float* x = (const float*)d_in[0];
    const float* t = (const float*)d_in[1];
    float* out = (float*)d_out;

    const int n  = in_sizes[0];
    const int n4 = n >> 2;

    int blocks = GRID;
    int needed = (n4 + TPB - 1) / TPB;
    if (needed < 1) needed = 1;
    if (blocks > needed) blocks = needed;

    ghm_fused_kernel<<<blocks, TPB>>>(
        (const float4*)x, (const float4*)t, x, t, n4, n, (long long)n, out);
}

// round 8
// speedup vs baseline: 1.1788x; 1.1788x over previous
#include <cuda_runtime.h>
#include <cuda_bf16.h>

#define BINS 10
#define TPB  256
#define CTAS_PER_SM 6
#define GRID (148 * CTAS_PER_SM)

// __device__ globals zero-initialized at load; last block resets them after
// finalizing -> every launch / graph replay starts clean. Single launch node.
__device__ double             g_loss_sum[BINS];
__device__ unsigned long long g_count[BINS];
__device__ unsigned int       g_ticket;

// One element's accumulate. 'slot' is the warp-private rotated slot index
// (warpbase + ((lane + phase) & 31)) -> breaks same-bin RMW chains between
// consecutive elements at zero smem cost, stays bank-conflict-free (lane
// bijection per phase) and warp-private (no cross-warp collisions).
__device__ __forceinline__ void ghm_elem(float2* __restrict__ acc, int slot,
                                         float xx, float tt)
{
    float g  = fabsf(xx - tt);
    int   b  = (int)(g * 9.9999f);          // g < 1 strictly -> b in [0,9]
    float l1 = __log2f(xx);
    float l2 = __log2f(1.0f - xx);
    float loss2 = fmaf(tt, l1 - l2, l2);    // scaled by -ln2 at finalize
    int addr = b * TPB + slot;
    float2 a = acc[addr];
    a.x += loss2;
    a.y += 1.0f;
    acc[addr] = a;
}

__global__ __launch_bounds__(TPB, CTAS_PER_SM)
void ghm_fused_kernel(const float4* __restrict__ x4,
                      const float4* __restrict__ t4,
                      const float*  __restrict__ x1,
                      const float*  __restrict__ t1,
                      int n4, int n, long long N,
                      float* __restrict__ out)
{
    __shared__ float2 acc[BINS * TPB];

    const int tid      = threadIdx.x;
    const int warpbase = tid & ~31;
    const int lane     = tid & 31;
    // rotated slots for the 4 element phases of each float4
    const int s0 = warpbase + ((lane + 0) & 31);
    const int s1 = warpbase + ((lane + 1) & 31);
    const int s2 = warpbase + ((lane + 2) & 31);
    const int s3 = warpbase + ((lane + 3) & 31);

#pragma unroll
    for (int k = 0; k < BINS; k++)
        acc[k * TPB + tid] = make_float2(0.0f, 0.0f);
    __syncthreads();

    const int stride = gridDim.x * blockDim.x;
    int i = blockIdx.x * blockDim.x + tid;

    // 3-stage software pipeline: keep 2 iterations of loads (4x LDG.128) in flight.
    if (i < n4) {
        float4 xv0 = x4[i];
        float4 tv0 = t4[i];
        float4 xv1, tv1;
        bool have1 = (i + stride < n4);
        if (have1) { xv1 = x4[i + stride]; tv1 = t4[i + stride]; }

        for (; i + 2 * stride < n4; i += stride) {
            float4 xn = x4[i + 2 * stride];
            float4 tn = t4[i + 2 * stride];
            ghm_elem(acc, s0, xv0.x, tv0.x);
            ghm_elem(acc, s1, xv0.y, tv0.y);
            ghm_elem(acc, s2, xv0.z, tv0.z);
            ghm_elem(acc, s3, xv0.w, tv0.w);
            xv0 = xv1; tv0 = tv1;
            xv1 = xn;  tv1 = tn;
        }
        // drain
        ghm_elem(acc, s0, xv0.x, tv0.x);
        ghm_elem(acc, s1, xv0.y, tv0.y);
        ghm_elem(acc, s2, xv0.z, tv0.z);
        ghm_elem(acc, s3, xv0.w, tv0.w);
        if (have1) {
            ghm_elem(acc, s0, xv1.x, tv1.x);
            ghm_elem(acc, s1, xv1.y, tv1.y);
            ghm_elem(acc, s2, xv1.z, tv1.z);
            ghm_elem(acc, s3, xv1.w, tv1.w);
        }
    }

    // scalar tail (n % 4): block 0 only
    if (blockIdx.x == 0) {
        for (int k = n4 * 4 + tid; k < n; k += blockDim.x)
            ghm_elem(acc, s0, x1[k], t1[k]);
    }
    __syncthreads();

    // block tree reduction over slot dimension for all bins
    for (int s = TPB / 2; s > 0; s >>= 1) {
        if (tid < s) {
#pragma unroll
            for (int k = 0; k < BINS; k++) {
                float2 a = acc[k * TPB + tid];
                float2 b = acc[k * TPB + tid + s];
                a.x += b.x; a.y += b.y;
                acc[k * TPB + tid] = a;
            }
        }
        __syncthreads();
    }

    if (tid < BINS) {
        float2 a = acc[tid * TPB];
        atomicAdd(&g_loss_sum[tid], (double)a.x);
        atomicAdd(&g_count[tid], (unsigned long long)(a.y + 0.5f));
    }

    // last-block finalize + reset (fused epilogue)
    __shared__ unsigned int s_is_last;
    if (tid == 0) {
        __threadfence();
        unsigned int prev = atomicAdd(&g_ticket, 1u);
        s_is_last = (prev == (unsigned int)gridDim.x - 1u) ? 1u : 0u;
    }
    __syncthreads();

    if (s_is_last && tid == 0) {
        __threadfence();                     // all blocks' atomics visible
        const double NEG_LN2 = -0.6931471805599453;
        float nonempty = 0.0f;
#pragma unroll
        for (int k = 0; k < BINS; k++)
            nonempty += (g_count[k] > 0ull) ? 1.0f : 0.0f;

        const float Nf = (float)N;
        double total = 0.0;
#pragma unroll
        for (int k = 0; k < BINS; k++) {
            float cntf = (float)g_count[k];              // match jnp f32 cast
            float gd   = fmaxf(cntf * nonempty, 1.0f);
            float beta = Nf / gd;
            total += (double)beta * (NEG_LN2 * g_loss_sum[k]);
        }
        out[0] = (float)(total / (double)N);

        // reset for next launch / graph replay
#pragma unroll
        for (int k = 0; k < BINS; k++) {
            g_loss_sum[k] = 0.0;
            g_count[k]    = 0ull;
        }
        __threadfence();
        g_ticket = 0u;
    }
}

extern "C" void kernel_launch(void* const* d_in, const int* in_sizes, int n_in,
                              void* d_out, int out_size)
{
    const float* x = (const float*)d_in[0];
    const float* t = (const float*)d_in[1];
    float* out = (float*)d_out;

    const int n  = in_sizes[0];
    const int n4 = n >> 2;

    int blocks = GRID;
    int needed = (n4 + TPB - 1) / TPB;
    if (needed < 1) needed = 1;
    if (blocks > needed) blocks = needed;

    ghm_fused_kernel<<<blocks, TPB>>>(
        (const float4*)x, (const float4*)t, x, t, n4, n, (long long)n, out);
}